// round 7
// baseline (speedup 1.0000x reference)
#include <cuda_runtime.h>
#include <cuda_bf16.h>

#define N_NODES 50000
#define N_EDGES 800000
#define D 64
#define SCAN_BLK 1024
#define SCAN_NB  ((N_NODES + 1 + SCAN_BLK - 1) / SCAN_BLK)   // 49

// ---- device-global scratch (no allocations allowed) ----
// Invariant at every kernel_launch entry: g_count == 0 and g_scan_flag == 0
// (BSS-zero initially; reset-after-consume inside the pipeline each call).
__device__ int   g_count[N_NODES];
__device__ int   g_off[N_NODES + 1];
__device__ int   g_cursor[N_NODES];
__device__ __align__(16) int2 g_perm[N_EDGES];   // (src, ex-bits), CSR order
__device__ volatile int g_scan_tot[SCAN_NB];
__device__ volatile int g_scan_flag[SCAN_NB];

// ---------------------------------------------------------------------------
// K1: degree histogram over dst (int4 loads, 4 edges/thread).
// ---------------------------------------------------------------------------
__global__ void kgcn_hist_kernel(const int* __restrict__ dst) {
    int t = blockIdx.x * blockDim.x + threadIdx.x;
    if (t < N_EDGES / 4) {
        int4 d4 = reinterpret_cast<const int4*>(dst)[t];
        atomicAdd(&g_count[d4.x], 1);
        atomicAdd(&g_count[d4.y], 1);
        atomicAdd(&g_count[d4.z], 1);
        atomicAdd(&g_count[d4.w], 1);
    }
}

// ---------------------------------------------------------------------------
// K2: single-kernel exclusive scan (decoupled lookback, 49 wave-1-resident
// blocks). Sets g_off / g_cursor, resets g_count for the next call.
// ---------------------------------------------------------------------------
__global__ void __launch_bounds__(SCAN_BLK) kgcn_scan_kernel() {
    __shared__ int wsum[32];
    __shared__ int s_prefix;
    const int tid = threadIdx.x, b = blockIdx.x;
    const int i = b * SCAN_BLK + tid;

    int v = (i < N_NODES) ? g_count[i] : 0;

    int lane = tid & 31, wid = tid >> 5;
    int x = v;
    #pragma unroll
    for (int dd = 1; dd < 32; dd <<= 1) {
        int y = __shfl_up_sync(0xffffffffu, x, dd);
        if (lane >= dd) x += y;
    }
    if (lane == 31) wsum[wid] = x;
    __syncthreads();
    if (wid == 0) {
        int s = wsum[lane];
        #pragma unroll
        for (int dd = 1; dd < 32; dd <<= 1) {
            int y = __shfl_up_sync(0xffffffffu, s, dd);
            if (lane >= dd) s += y;
        }
        wsum[lane] = s;
    }
    __syncthreads();
    int incl = x + ((wid > 0) ? wsum[wid - 1] : 0);

    if (tid == SCAN_BLK - 1) {
        g_scan_tot[b] = incl;
        __threadfence();
        g_scan_flag[b] = 1;
    }

    if (tid < 32) {
        int sum = 0;
        for (int j = tid; j < b; j += 32) {
            while (g_scan_flag[j] == 0) { }
            sum += g_scan_tot[j];
        }
        #pragma unroll
        for (int o = 16; o; o >>= 1) sum += __shfl_xor_sync(0xffffffffu, sum, o);
        if (tid == 0) s_prefix = sum;
    }
    __syncthreads();

    int off = s_prefix + incl - v;
    if (i <= N_NODES) {
        g_off[i] = off;
        if (i < N_NODES) {
            g_cursor[i] = off;
            g_count[i] = 0;           // reset-after-consume
        }
    }
}

// ---------------------------------------------------------------------------
// K3: FUSED score+scatter. Half-warp (16 lanes x float4) per edge:
//   ex = exp(dot(h_src[src], e))            (e streamed sequentially: DRAM BW)
//   pos = cursor[dst]++;  perm[pos] = (src, ex)
// Also resets the scan flags for the next call.
// ---------------------------------------------------------------------------
__global__ void kgcn_score_kernel(const float* __restrict__ h_src,
                                  const float* __restrict__ e,
                                  const int* __restrict__ src,
                                  const int* __restrict__ dst) {
    int tid  = blockIdx.x * blockDim.x + threadIdx.x;
    if (tid < SCAN_NB) g_scan_flag[tid] = 0;          // reset-after-consume
    int edge = tid >> 4;
    int sub  = tid & 15;
    if (edge >= N_EDGES) return;   // never taken: E*16 == grid exactly

    int s = src[edge];
    float4 hv = reinterpret_cast<const float4*>(h_src)[(size_t)s * 16 + sub];
    float4 ev = reinterpret_cast<const float4*>(e)[(size_t)edge * 16 + sub];

    float dot = hv.x * ev.x + hv.y * ev.y + hv.z * ev.z + hv.w * ev.w;
    dot += __shfl_xor_sync(0xffffffffu, dot, 1);
    dot += __shfl_xor_sync(0xffffffffu, dot, 2);
    dot += __shfl_xor_sync(0xffffffffu, dot, 4);
    dot += __shfl_xor_sync(0xffffffffu, dot, 8);

    if (sub == 0) {
        int d = dst[edge];
        int pos = atomicAdd(&g_cursor[d], 1);
        g_perm[pos] = make_int2(s, __float_as_int(__expf(dot)));
    }
}

// ---------------------------------------------------------------------------
// K4: FUSED pull + output GEMM. Block owns 64 nodes:
//   1) stage h_dst rows into h_all[node][0..63]
//   2) pull-aggregate in-edges (16 lanes/node, register acc, baked-in ex),
//      write normalized result into h_all[node][64..127]
//   3) register-tiled GEMM out = h_all @ W^T + b, W staged per 32-k chunk.
// smem: 64*129*4 = 33KB (h_all) + 32*64*4 = 8KB (W chunk) = 41.2KB.
// ---------------------------------------------------------------------------
#define HA_STRIDE 129
__global__ void __launch_bounds__(256) kgcn_pullgemm_kernel(
        const float* __restrict__ h_src,
        const float* __restrict__ h_dst,
        const float* __restrict__ W,
        const float* __restrict__ b,
        float* __restrict__ out) {
    __shared__ float h_all[64 * HA_STRIDE];   // [local node][k 0..127]
    __shared__ float W_c[32 * 64];            // current chunk, [kk][j]

    const int tid = threadIdx.x;
    const int node0 = blockIdx.x * 64;
    const int sub = tid & 15;

    // --- stage h_dst: 64 nodes x 16 float4 = 1024 loads, coalesced ---
    #pragma unroll
    for (int r = 0; r < 4; r++) {
        int idx = tid + r * 256;      // 0..1023
        int n   = idx >> 4;           // local node
        int q   = idx & 15;           // float4 slot
        int gn  = node0 + n;
        float4 v = make_float4(0.f, 0.f, 0.f, 0.f);
        if (gn < N_NODES)
            v = reinterpret_cast<const float4*>(h_dst)[(size_t)gn * 16 + q];
        int base = n * HA_STRIDE + q * 4;
        h_all[base + 0] = v.x; h_all[base + 1] = v.y;
        h_all[base + 2] = v.z; h_all[base + 3] = v.w;
    }

    // --- pull phase: 4 passes x 16 nodes (16 lanes each) ---
    const float4* h4 = reinterpret_cast<const float4*>(h_src);
    #pragma unroll
    for (int p = 0; p < 4; p++) {
        int ln = p * 16 + (tid >> 4);     // local node 0..63
        int gn = node0 + ln;
        float4 acc = make_float4(0.f, 0.f, 0.f, 0.f);
        float den = 0.f;
        if (gn < N_NODES) {
            int beg = g_off[gn];
            int end = g_off[gn + 1];
            int i = beg;
            for (; i + 1 < end; i += 2) {
                int2 a = g_perm[i];
                int2 c = g_perm[i + 1];
                float4 h0 = h4[(size_t)a.x * 16 + sub];
                float4 h1 = h4[(size_t)c.x * 16 + sub];
                float e0 = __int_as_float(a.y);
                float e1 = __int_as_float(c.y);
                den += e0 + e1;
                acc.x = fmaf(e0, h0.x, acc.x); acc.y = fmaf(e0, h0.y, acc.y);
                acc.z = fmaf(e0, h0.z, acc.z); acc.w = fmaf(e0, h0.w, acc.w);
                acc.x = fmaf(e1, h1.x, acc.x); acc.y = fmaf(e1, h1.y, acc.y);
                acc.z = fmaf(e1, h1.z, acc.z); acc.w = fmaf(e1, h1.w, acc.w);
            }
            if (i < end) {
                int2 a = g_perm[i];
                float4 h0 = h4[(size_t)a.x * 16 + sub];
                float e0 = __int_as_float(a.y);
                den += e0;
                acc.x = fmaf(e0, h0.x, acc.x); acc.y = fmaf(e0, h0.y, acc.y);
                acc.z = fmaf(e0, h0.z, acc.z); acc.w = fmaf(e0, h0.w, acc.w);
            }
        }
        float inv = (den > 0.f) ? (1.0f / den) : 0.f;   // degree-0 -> 0
        int base = ln * HA_STRIDE + 64 + sub * 4;
        h_all[base + 0] = acc.x * inv; h_all[base + 1] = acc.y * inv;
        h_all[base + 2] = acc.z * inv; h_all[base + 3] = acc.w * inv;
    }

    // --- GEMM: thread tile 4 nodes x 4 cols ---
    const int tx = tid & 15;      // cols 4*tx..4*tx+3
    const int ty = tid >> 4;      // nodes 4*ty..4*ty+3

    float acc[4][4];
    #pragma unroll
    for (int n = 0; n < 4; n++)
        acc[n][0] = acc[n][1] = acc[n][2] = acc[n][3] = 0.f;

    #pragma unroll
    for (int c = 0; c < 4; c++) {
        __syncthreads();   // c==0: h_all ready; c>0: previous W_c readers done
        // stage W chunk c transposed: W_c[kk][j] = W[j*128 + c*32 + kk]
        for (int i = tid; i < 32 * 64; i += 256) {
            int kk = i >> 6;
            int j  = i & 63;
            W_c[i] = W[j * 128 + c * 32 + kk];
        }
        __syncthreads();

        const float* Wrow = &W_c[4 * tx];
        #pragma unroll 8
        for (int kk = 0; kk < 32; kk++) {
            float4 w = *reinterpret_cast<const float4*>(Wrow + kk * 64);
            #pragma unroll
            for (int n = 0; n < 4; n++) {
                float hv = h_all[(4 * ty + n) * HA_STRIDE + c * 32 + kk];
                acc[n][0] = fmaf(hv, w.x, acc[n][0]);
                acc[n][1] = fmaf(hv, w.y, acc[n][1]);
                acc[n][2] = fmaf(hv, w.z, acc[n][2]);
                acc[n][3] = fmaf(hv, w.w, acc[n][3]);
            }
        }
    }

    float4 bb = *reinterpret_cast<const float4*>(&b[4 * tx]);
    #pragma unroll
    for (int n = 0; n < 4; n++) {
        int gn = node0 + 4 * ty + n;
        if (gn < N_NODES) {
            float4 o = make_float4(acc[n][0] + bb.x, acc[n][1] + bb.y,
                                   acc[n][2] + bb.z, acc[n][3] + bb.w);
            reinterpret_cast<float4*>(out)[(size_t)gn * 16 + tx] = o;
        }
    }
}

// ---------------------------------------------------------------------------
// Launch.  Inputs: 0 h_src, 1 h_dst, 2 e, 3 src, 4 dst, 5 W, 6 b
// ---------------------------------------------------------------------------
extern "C" void kernel_launch(void* const* d_in, const int* in_sizes, int n_in,
                              void* d_out, int out_size) {
    const float* h_src = (const float*)d_in[0];
    const float* h_dst = (const float*)d_in[1];
    const float* e     = (const float*)d_in[2];
    const int*   src   = (const int*)d_in[3];
    const int*   dst   = (const int*)d_in[4];
    const float* W     = (const float*)d_in[5];
    const float* b     = (const float*)d_in[6];
    float* out = (float*)d_out;

    kgcn_hist_kernel<<<(N_EDGES / 4 + 255) / 256, 256>>>(dst);
    kgcn_scan_kernel<<<SCAN_NB, SCAN_BLK>>>();
    kgcn_score_kernel<<<50000, 256>>>(h_src, e, src, dst);   // 16 thr/edge
    kgcn_pullgemm_kernel<<<(N_NODES + 63) / 64, 256>>>(h_src, h_dst, W, b, out);
}

// round 8
// speedup vs baseline: 1.5823x; 1.5823x over previous
#include <cuda_runtime.h>
#include <cuda_bf16.h>

#define N_NODES 50000
#define N_EDGES 800000
#define D 64

// ---- device-global scratch (no allocations allowed) ----
__device__ __align__(16) float g_denom[N_NODES];
__device__ __align__(16) float g_hunnorm[N_NODES * D];   // un-normalized msg sums

// ---------------------------------------------------------------------------
// Zero accumulators (13MB) — reruns every launch (graph replays).
// ---------------------------------------------------------------------------
__global__ void kgcn_zero_kernel() {
    int i = blockIdx.x * blockDim.x + threadIdx.x;
    int stride = gridDim.x * blockDim.x;
    float4 z = make_float4(0.f, 0.f, 0.f, 0.f);
    float4* h4 = reinterpret_cast<float4*>(g_hunnorm);
    const int TOT_H4 = N_NODES * D / 4;
    for (int idx = i; idx < TOT_H4; idx += stride) h4[idx] = z;
    float4* d4 = reinterpret_cast<float4*>(g_denom);
    const int TOT_D4 = N_NODES / 4;
    for (int idx = i; idx < TOT_D4; idx += stride) d4[idx] = z;
}

// ---------------------------------------------------------------------------
// Fused edge kernel, 2 edges per half-warp for MLP:
//   4 independent 16B loads in flight, two interleaved shfl-reduce chains,
//   ex = exp(dot);  hunnorm[dst] += ex*hv (red.v4);  denom[dst] += ex.
// e rows are read sequentially (warp covers 4 consecutive edges = 1KB).
// Normalization deferred to the GEMM.
// ---------------------------------------------------------------------------
__global__ void kgcn_edge_kernel(const float* __restrict__ h_src,
                                 const float* __restrict__ e,
                                 const int* __restrict__ src,
                                 const int* __restrict__ dst) {
    int tid = blockIdx.x * blockDim.x + threadIdx.x;
    int grp = tid >> 4;          // half-warp group id
    int sub = tid & 15;
    int e0 = grp * 2;            // groups = 400000, exactly covered
    int e1 = e0 + 1;

    int s0 = src[e0], s1 = src[e1];
    int d0 = dst[e0], d1 = dst[e1];

    const float4* h4 = reinterpret_cast<const float4*>(h_src);
    const float4* e4 = reinterpret_cast<const float4*>(e);
    float4 ev0 = e4[(size_t)e0 * 16 + sub];
    float4 ev1 = e4[(size_t)e1 * 16 + sub];
    float4 hv0 = h4[(size_t)s0 * 16 + sub];
    float4 hv1 = h4[(size_t)s1 * 16 + sub];

    float dot0 = hv0.x * ev0.x + hv0.y * ev0.y + hv0.z * ev0.z + hv0.w * ev0.w;
    float dot1 = hv1.x * ev1.x + hv1.y * ev1.y + hv1.z * ev1.z + hv1.w * ev1.w;

    // interleaved xor-reductions (independent chains overlap SHFL latency)
    dot0 += __shfl_xor_sync(0xffffffffu, dot0, 1);
    dot1 += __shfl_xor_sync(0xffffffffu, dot1, 1);
    dot0 += __shfl_xor_sync(0xffffffffu, dot0, 2);
    dot1 += __shfl_xor_sync(0xffffffffu, dot1, 2);
    dot0 += __shfl_xor_sync(0xffffffffu, dot0, 4);
    dot1 += __shfl_xor_sync(0xffffffffu, dot1, 4);
    dot0 += __shfl_xor_sync(0xffffffffu, dot0, 8);
    dot1 += __shfl_xor_sync(0xffffffffu, dot1, 8);

    float ex0 = __expf(dot0);
    float ex1 = __expf(dot1);

    float* a0 = &g_hunnorm[(size_t)d0 * D + sub * 4];
    float* a1 = &g_hunnorm[(size_t)d1 * D + sub * 4];
    asm volatile("red.global.add.v4.f32 [%0], {%1, %2, %3, %4};"
                 :: "l"(a0), "f"(ex0 * hv0.x), "f"(ex0 * hv0.y),
                    "f"(ex0 * hv0.z), "f"(ex0 * hv0.w) : "memory");
    asm volatile("red.global.add.v4.f32 [%0], {%1, %2, %3, %4};"
                 :: "l"(a1), "f"(ex1 * hv1.x), "f"(ex1 * hv1.y),
                    "f"(ex1 * hv1.z), "f"(ex1 * hv1.w) : "memory");
    if (sub == 0) {
        atomicAdd(&g_denom[d0], ex0);
        atomicAdd(&g_denom[d1], ex1);
    }
}

// ---------------------------------------------------------------------------
// Output GEMM: out = concat(h_dst, hunnorm/denom) @ W^T + b
// Block: 256 threads -> 64-node x 64-col tile; thread: 4 nodes x 4 cols.
// Normalization folded into the staging of chunks 2-3. (Measured ~30us in R4.)
// ---------------------------------------------------------------------------
#define HS_STRIDE 33
__global__ void __launch_bounds__(256) kgcn_out_kernel(
        const float* __restrict__ h_dst,
        const float* __restrict__ W,
        const float* __restrict__ b,
        float* __restrict__ out) {
    __shared__ float W_s[128 * 64];          // [k][j] transposed, 32KB
    __shared__ float h_s[64 * HS_STRIDE];    // [local node][kk], padded

    const int tid = threadIdx.x;
    for (int i = tid; i < 64 * 128; i += 256) {
        int j = i >> 7;
        int k = i & 127;
        W_s[k * 64 + j] = W[i];
    }

    const int tx = tid & 15;      // cols 4*tx..4*tx+3
    const int ty = tid >> 4;      // nodes 4*ty..4*ty+3
    const int node0 = blockIdx.x * 64;

    float acc[4][4];
    #pragma unroll
    for (int n = 0; n < 4; n++)
        acc[n][0] = acc[n][1] = acc[n][2] = acc[n][3] = 0.f;

    #pragma unroll
    for (int c = 0; c < 4; c++) {
        const float* srcp = (c < 2) ? h_dst : g_hunnorm;
        const int kof4 = (c & 1) * 8;

        __syncthreads();
        #pragma unroll
        for (int r = 0; r < 2; r++) {
            int idx = tid + r * 256;    // 0..511
            int n   = idx >> 3;
            int q   = idx & 7;
            int gn  = node0 + n;
            float4 v = make_float4(0.f, 0.f, 0.f, 0.f);
            if (gn < N_NODES) {
                v = reinterpret_cast<const float4*>(srcp)[(size_t)gn * 16 + kof4 + q];
                if (c >= 2) {
                    float dn = g_denom[gn];
                    float inv = (dn != 0.f) ? (1.0f / dn) : 0.f;  // edge-less -> 0
                    v.x *= inv; v.y *= inv; v.z *= inv; v.w *= inv;
                }
            }
            int base = n * HS_STRIDE + q * 4;
            h_s[base + 0] = v.x; h_s[base + 1] = v.y;
            h_s[base + 2] = v.z; h_s[base + 3] = v.w;
        }
        __syncthreads();

        const float* Wrow = &W_s[(c * 32) * 64 + 4 * tx];
        #pragma unroll 8
        for (int kk = 0; kk < 32; kk++) {
            float4 w = *reinterpret_cast<const float4*>(Wrow + kk * 64);
            #pragma unroll
            for (int n = 0; n < 4; n++) {
                float hv = h_s[(4 * ty + n) * HS_STRIDE + kk];
                acc[n][0] = fmaf(hv, w.x, acc[n][0]);
                acc[n][1] = fmaf(hv, w.y, acc[n][1]);
                acc[n][2] = fmaf(hv, w.z, acc[n][2]);
                acc[n][3] = fmaf(hv, w.w, acc[n][3]);
            }
        }
    }

    float4 bb = *reinterpret_cast<const float4*>(&b[4 * tx]);
    #pragma unroll
    for (int n = 0; n < 4; n++) {
        int gn = node0 + 4 * ty + n;
        if (gn < N_NODES) {
            float4 o = make_float4(acc[n][0] + bb.x, acc[n][1] + bb.y,
                                   acc[n][2] + bb.z, acc[n][3] + bb.w);
            reinterpret_cast<float4*>(out)[(size_t)gn * 16 + tx] = o;
        }
    }
}

// ---------------------------------------------------------------------------
// Launch.  Inputs: 0 h_src, 1 h_dst, 2 e, 3 src, 4 dst, 5 W, 6 b
// ---------------------------------------------------------------------------
extern "C" void kernel_launch(void* const* d_in, const int* in_sizes, int n_in,
                              void* d_out, int out_size) {
    const float* h_src = (const float*)d_in[0];
    const float* h_dst = (const float*)d_in[1];
    const float* e     = (const float*)d_in[2];
    const int*   src   = (const int*)d_in[3];
    const int*   dst   = (const int*)d_in[4];
    const float* W     = (const float*)d_in[5];
    const float* b     = (const float*)d_in[6];
    float* out = (float*)d_out;

    kgcn_zero_kernel<<<1184, 256>>>();
    // 400000 half-warp groups * 2 edges; 16 groups per 256-thread block
    kgcn_edge_kernel<<<25000, 256>>>(h_src, e, src, dst);
    kgcn_out_kernel<<<(N_NODES + 63) / 64, 256>>>(h_dst, W, b, out);
}